// round 4
// baseline (speedup 1.0000x reference)
#include <cuda_runtime.h>

// Problem constants
#define B_    8
#define K_    64
#define L_    1024
#define CP_   32
#define CSA_  16
#define NOC1  256
#define K1    576          // K_*G2_
#define NCH   36           // K1/16 chunks

typedef unsigned long long ull;

// Packed fp32x2 helpers (sm_100+)
#define FFMA2(acc, a, b) asm("fma.rn.f32x2 %0, %1, %2, %0;" : "+l"(acc) : "l"(a), "l"(b))
#define PACK2(dst, f)    asm("mov.b64 %0, {%1, %1};" : "=l"(dst) : "f"(f))
#define UNPACK2(lo, hi, v) asm("mov.b64 {%0, %1}, %2;" : "=f"(lo), "=f"(hi) : "l"(v))

// Scratch (allocation-free: device global)
__device__ float g_yq[B_ * L_ * NOC1];      // squashed conv1 output [B, L, 256]

// ---------------------------------------------------------------------------
// Kernel 1: conv1 (implicit GEMM, 'SAME') + bias + squash.
// 256 threads, 32 l x 256 oc per block; thread: 2l x 16oc (FFMA2 accs).
// Weights transposed in-kernel; double-buffered, LDG overlapped with compute.
// ---------------------------------------------------------------------------
__global__ __launch_bounds__(256) void conv1_squash_kernel(
    const float* __restrict__ x, const float* __restrict__ w1,
    const float* __restrict__ b1)
{
    __shared__ float xs[K_][40];          // 64 ic x (32 + 8 halo)
    __shared__ float wbuf[2][16][NOC1];   // double-buffered weight chunks
    float (*ysh)[NOC1] = (float(*)[NOC1])wbuf;  // epilogue alias (16x256)
    __shared__ float b1s[NOC1];

    const int b  = blockIdx.y;
    const int l0 = blockIdx.x * 32;
    const int t  = threadIdx.x;

    b1s[t] = b1[t];
    for (int i = t; i < K_ * 40; i += 256) {
        int ic = i / 40, jj = i - ic * 40;
        int l = l0 - 4 + jj;
        xs[ic][jj] = (l >= 0 && l < L_) ? x[(b * K_ + ic) * L_ + l] : 0.f;
    }

    // Thread owns oc = t for weight staging: w1[t][k] row
    const float4* wrow = (const float4*)(w1 + t * K1);
    float4 wr[4];
#pragma unroll
    for (int i = 0; i < 4; i++) wr[i] = wrow[i];          // k = 0..15
#pragma unroll
    for (int i = 0; i < 4; i++) {
        wbuf[0][i * 4 + 0][t] = wr[i].x;
        wbuf[0][i * 4 + 1][t] = wr[i].y;
        wbuf[0][i * 4 + 2][t] = wr[i].z;
        wbuf[0][i * 4 + 3][t] = wr[i].w;
    }

    ull acc2[2][8];
#pragma unroll
    for (int j = 0; j < 2; j++)
#pragma unroll
        for (int i = 0; i < 8; i++) acc2[j][i] = 0ULL;

    const int lg = t >> 4;   // 0..15 -> l = lg*2 + {0,1}
    const int og = t & 15;   // oc = og*4 + q*64 + {0..3}
    __syncthreads();

    for (int c = 0; c < NCH; c++) {
        const int cur = c & 1;
        // prefetch next chunk into regs (overlaps with compute below)
        if (c + 1 < NCH) {
#pragma unroll
            for (int i = 0; i < 4; i++) wr[i] = wrow[(c + 1) * 4 + i];
        }
#pragma unroll
        for (int kk = 0; kk < 16; kk++) {
            int k  = c * 16 + kk;
            int ic = k / 9;
            int tt = k - ic * 9;
            float xv0 = xs[ic][lg * 2 + tt];
            float xv1 = xs[ic][lg * 2 + 1 + tt];
            ull X0, X1;
            PACK2(X0, xv0);
            PACK2(X1, xv1);
#pragma unroll
            for (int q = 0; q < 4; q++) {
                ulonglong2 wq = *(const ulonglong2*)&wbuf[cur][kk][og * 4 + q * 64];
                FFMA2(acc2[0][q * 2 + 0], X0, wq.x);
                FFMA2(acc2[0][q * 2 + 1], X0, wq.y);
                FFMA2(acc2[1][q * 2 + 0], X1, wq.x);
                FFMA2(acc2[1][q * 2 + 1], X1, wq.y);
            }
        }
        if (c + 1 < NCH) {
#pragma unroll
            for (int i = 0; i < 4; i++) {
                wbuf[cur ^ 1][i * 4 + 0][t] = wr[i].x;
                wbuf[cur ^ 1][i * 4 + 1][t] = wr[i].y;
                wbuf[cur ^ 1][i * 4 + 2][t] = wr[i].z;
                wbuf[cur ^ 1][i * 4 + 3][t] = wr[i].w;
            }
        }
        __syncthreads();
    }

    // Epilogue: two passes of 16 l through ysh (aliases wbuf), squash, store.
#pragma unroll
    for (int pass = 0; pass < 2; pass++) {
        if ((lg >> 3) == pass) {
            int lb = (lg & 7) * 2;
#pragma unroll
            for (int j = 0; j < 2; j++)
#pragma unroll
                for (int q = 0; q < 4; q++)
#pragma unroll
                    for (int h = 0; h < 2; h++) {
                        float lo, hi;
                        UNPACK2(lo, hi, acc2[j][q * 2 + h]);
                        int oc = og * 4 + q * 64 + h * 2;
                        ysh[lb + j][oc]     = lo + b1s[oc];
                        ysh[lb + j][oc + 1] = hi + b1s[oc + 1];
                    }
        }
        __syncthreads();
        for (int g = t; g < 512; g += 256) {
            int l_loc = g >> 5, cp = g & 31;
            float4 a = *(const float4*)&ysh[l_loc][cp * 8];
            float4 c = *(const float4*)&ysh[l_loc][cp * 8 + 4];
            float sq = a.x * a.x + a.y * a.y + a.z * a.z + a.w * a.w
                     + c.x * c.x + c.y * c.y + c.z * c.z + c.w * c.w;
            float scale = sq / (1.f + sq) * rsqrtf(sq + 1e-8f);
            a.x *= scale; a.y *= scale; a.z *= scale; a.w *= scale;
            c.x *= scale; c.y *= scale; c.z *= scale; c.w *= scale;
            int l = l0 + pass * 16 + l_loc;
            float* dst = &g_yq[((size_t)(b * L_ + l)) * NOC1 + cp * 8];
            *(float4*)dst       = a;
            *(float4*)(dst + 4) = c;
        }
        __syncthreads();
    }
}

// ---------------------------------------------------------------------------
// Kernel 2: conv2 -> V in registers, 3-iter routing.
// Parallel softmax (no max-sub; values bounded), butterfly b-update.
// One block per (b,l). Thread t = (csa, asa).
// ---------------------------------------------------------------------------
__global__ __launch_bounds__(256) void conv2_route_kernel(
    const float* __restrict__ w2, const float* __restrict__ b2,
    float* __restrict__ out)
{
    __shared__ float yq3[3][NOC1];
    __shared__ float bf[512];       // routing logits, flat [cp][csa]
    __shared__ float ef[512];       // exp(logits)
    __shared__ float sinv[CP_];     // 1/rowsum

    const int bl = blockIdx.x;
    const int l  = bl & (L_ - 1);
    const int t  = threadIdx.x;

    const float* base = g_yq + (size_t)bl * NOC1;
    yq3[1][t] = base[t];
    yq3[0][t] = (l > 0)      ? base[t - NOC1] : 0.f;
    yq3[2][t] = (l < L_ - 1) ? base[t + NOC1] : 0.f;

    // packed conv2 weights: w2p[h] = {w2[t][2h], w2[t][2h+1]}  (contiguous)
    ull w2p[12];
    const float2* wrow = (const float2*)(w2 + t * 24);
#pragma unroll
    for (int h = 0; h < 12; h++) {
        float2 wv = wrow[h];
        asm("mov.b64 %0, {%1, %2};" : "=l"(w2p[h]) : "f"(wv.x), "f"(wv.y));
    }
    const float bias = b2[t];

    bf[t]       = 0.f;
    bf[t + 256] = 0.f;
    __syncthreads();

    // V[cp] for this thread's (csa, asa)
    float V[CP_];
#pragma unroll
    for (int cp = 0; cp < CP_; cp++) {
        ull acc;
        asm("mov.b64 %0, {%1, %2};" : "=l"(acc) : "f"(bias), "f"(0.f));
#pragma unroll
        for (int dh = 0; dh < 3; dh++) {
            const ulonglong2* yp = (const ulonglong2*)&yq3[dh][cp * 8];
            ulonglong2 ya = yp[0];
            ulonglong2 yb = yp[1];
            FFMA2(acc, ya.x, w2p[dh * 4 + 0]);
            FFMA2(acc, ya.y, w2p[dh * 4 + 1]);
            FFMA2(acc, yb.x, w2p[dh * 4 + 2]);
            FFMA2(acc, yb.y, w2p[dh * 4 + 3]);
        }
        float lo, hi;
        UNPACK2(lo, hi, acc);
        V[cp] = lo + hi;
    }

    const int csa = t >> 4;
    const int asa = t & 15;
    float v = 0.f;

    for (int r = 0; r < 3; r++) {
        float s;
        if (r == 0) {
            s = 0.f;
#pragma unroll
            for (int cp = 0; cp < CP_; cp++) s += V[cp];
            s *= (1.f / 16.f);
        } else {
            // parallel softmax over csa per cp-row (no max-sub: |b| is small)
            ef[t]       = __expf(bf[t]);
            ef[t + 256] = __expf(bf[t + 256]);
            __syncthreads();
            if (t < CP_) {
                float sum = 0.f;
#pragma unroll
                for (int j2 = 0; j2 < CSA_; j2++) sum += ef[t * 16 + j2];
                sinv[t] = 1.f / sum;
            }
            __syncthreads();
            s = 0.f;
#pragma unroll
            for (int cp = 0; cp < CP_; cp++)
                s += ef[cp * 16 + csa] * (sinv[cp] * V[cp]);
        }

        // squash over asa (16 contiguous lanes)
        float sq = s * s;
        sq += __shfl_xor_sync(0xffffffffu, sq, 1);
        sq += __shfl_xor_sync(0xffffffffu, sq, 2);
        sq += __shfl_xor_sync(0xffffffffu, sq, 4);
        sq += __shfl_xor_sync(0xffffffffu, sq, 8);
        float scale = sq / (1.f + sq) * rsqrtf(sq + 1e-8f);
        v = s * scale;

        if (r < 2) {
            // a[cp][csa] = sum_asa V*v via multi-value butterfly (30 shfl).
            float val[16];
            {
                bool u = (asa & 1);
#pragma unroll
                for (int i = 0; i < 16; i++) {
                    float sp = (u ? V[i] : V[16 + i]) * v;
                    float kp = (u ? V[16 + i] : V[i]) * v;
                    val[i] = kp + __shfl_xor_sync(0xffffffffu, sp, 1);
                }
            }
            {
                bool u = (asa & 2);
#pragma unroll
                for (int i = 0; i < 8; i++) {
                    float sp = u ? val[i] : val[8 + i];
                    float kp = u ? val[8 + i] : val[i];
                    val[i] = kp + __shfl_xor_sync(0xffffffffu, sp, 2);
                }
            }
            {
                bool u = (asa & 4);
#pragma unroll
                for (int i = 0; i < 4; i++) {
                    float sp = u ? val[i] : val[4 + i];
                    float kp = u ? val[4 + i] : val[i];
                    val[i] = kp + __shfl_xor_sync(0xffffffffu, sp, 4);
                }
            }
            {
                bool u = (asa & 8);
#pragma unroll
                for (int i = 0; i < 2; i++) {
                    float sp = u ? val[i] : val[2 + i];
                    float kp = u ? val[2 + i] : val[i];
                    val[i] = kp + __shfl_xor_sync(0xffffffffu, sp, 8);
                }
            }
            int c0 = ((asa & 1) << 4) | ((asa & 2) << 2) | (asa & 4) | ((asa & 8) >> 2);
            bf[c0 * 16 + csa]       += val[0];
            bf[(c0 + 1) * 16 + csa] += val[1];
            __syncthreads();
        }
    }

    out[(size_t)bl * 256 + t] = v;
}

// ---------------------------------------------------------------------------
extern "C" void kernel_launch(void* const* d_in, const int* in_sizes, int n_in,
                              void* d_out, int out_size)
{
    const float* x  = (const float*)d_in[0];   // [8, 64, 1024]
    const float* w1 = (const float*)d_in[1];   // [256, 64, 9]
    const float* b1 = (const float*)d_in[2];   // [256]
    const float* w2 = (const float*)d_in[3];   // [256, 1, 3, 8]
    const float* b2 = (const float*)d_in[4];   // [256]
    float* out = (float*)d_out;                // [8, 16384, 16]

    conv1_squash_kernel<<<dim3(L_ / 32, B_), 256>>>(x, w1, b1);
    conv2_route_kernel<<<B_ * L_, 256>>>(w2, b2, out);
}

// round 5
// speedup vs baseline: 1.1590x; 1.1590x over previous
#include <cuda_runtime.h>

// Problem constants
#define B_    8
#define K_    64
#define L_    1024
#define CP_   32
#define CSA_  16
#define NOC1  256
#define K1    576          // K_*G2_

typedef unsigned long long ull;

// Packed fp32x2 helpers (sm_100+)
#define FFMA2(acc, a, b) asm("fma.rn.f32x2 %0, %1, %2, %0;" : "+l"(acc) : "l"(a), "l"(b))
#define PACK2(dst, f)    asm("mov.b64 %0, {%1, %1};" : "=l"(dst) : "f"(f))
#define UNPACK2(lo, hi, v) asm("mov.b64 {%0, %1}, %2;" : "=f"(lo), "=f"(hi) : "l"(v))

// Scratch (allocation-free: device globals)
__device__ float g_yq[B_ * L_ * NOC1];      // squashed conv1 output [B, L, 256]
__device__ float g_wT[K1 * NOC1];           // conv1 weights transposed [k][oc]

// ---------------------------------------------------------------------------
// Prep: transpose conv1 weights for coalesced streaming
// ---------------------------------------------------------------------------
__global__ void prep_kernel(const float* __restrict__ w1) {
    int idx = blockIdx.x * 256 + threadIdx.x;
    if (idx < K1 * NOC1) {
        int k = idx >> 8, oc = idx & 255;
        g_wT[idx] = w1[oc * K1 + k];
    }
}

// ---------------------------------------------------------------------------
// Kernel 1: conv1 (implicit GEMM, 'SAME') + bias + squash. FFMA2 inner loop.
// Block: 16 l x 256 oc, 128 threads. Thread: 2l x 16oc. Grid: 512 blocks.
// (proven R3 shape: coalesced weight streaming via g_wT)
// ---------------------------------------------------------------------------
__global__ __launch_bounds__(128) void conv1_squash_kernel(
    const float* __restrict__ x, const float* __restrict__ b1)
{
    __shared__ float xs[K_][24];      // 64 ic x (16 + 8 halo)
    __shared__ float ws[16][NOC1];    // weight chunk (16 k rows)
    __shared__ float ysh[16][NOC1];   // staging for squash
    __shared__ float b1s[NOC1];

    const int b  = blockIdx.y;
    const int l0 = blockIdx.x * 16;
    const int t  = threadIdx.x;

    b1s[t]       = b1[t];
    b1s[t + 128] = b1[t + 128];
    for (int i = t; i < K_ * 24; i += 128) {
        int ic = i / 24, jj = i - ic * 24;
        int l = l0 - 4 + jj;
        xs[ic][jj] = (l >= 0 && l < L_) ? x[(b * K_ + ic) * L_ + l] : 0.f;
    }

    ull acc2[2][8];
#pragma unroll
    for (int j = 0; j < 2; j++)
#pragma unroll
        for (int i = 0; i < 8; i++) acc2[j][i] = 0ULL;

    const int lg = t >> 4;   // 0..7 -> l = lg*2 + {0,1}
    const int og = t & 15;   // oc = og*4 + q*64 + {0..3}
    __syncthreads();

    const float4* wT4 = (const float4*)g_wT;
    for (int kc = 0; kc < K1; kc += 16) {
#pragma unroll
        for (int i = 0; i < 8; i++)
            ((float4*)ws)[t + i * 128] = wT4[kc * 64 + t + i * 128];
        __syncthreads();
#pragma unroll
        for (int kk = 0; kk < 16; kk++) {
            int k  = kc + kk;
            int ic = k / 9;
            int tt = k - ic * 9;
            float xv0 = xs[ic][lg * 2 + tt];
            float xv1 = xs[ic][lg * 2 + 1 + tt];
            ull X0, X1;
            PACK2(X0, xv0);
            PACK2(X1, xv1);
#pragma unroll
            for (int q = 0; q < 4; q++) {
                ulonglong2 wq = *(const ulonglong2*)&ws[kk][og * 4 + q * 64];
                FFMA2(acc2[0][q * 2 + 0], X0, wq.x);
                FFMA2(acc2[0][q * 2 + 1], X0, wq.y);
                FFMA2(acc2[1][q * 2 + 0], X1, wq.x);
                FFMA2(acc2[1][q * 2 + 1], X1, wq.y);
            }
        }
        __syncthreads();
    }

    // Epilogue: stage y+bias, squash per 8-group, write g_yq
#pragma unroll
    for (int j = 0; j < 2; j++)
#pragma unroll
        for (int q = 0; q < 4; q++)
#pragma unroll
            for (int h = 0; h < 2; h++) {
                float lo, hi;
                UNPACK2(lo, hi, acc2[j][q * 2 + h]);
                int oc = og * 4 + q * 64 + h * 2;
                ysh[lg * 2 + j][oc]     = lo + b1s[oc];
                ysh[lg * 2 + j][oc + 1] = hi + b1s[oc + 1];
            }
    __syncthreads();
#pragma unroll
    for (int g = t; g < 512; g += 128) {
        int l_loc = g >> 5, cp = g & 31;
        float4 a = *(const float4*)&ysh[l_loc][cp * 8];
        float4 c = *(const float4*)&ysh[l_loc][cp * 8 + 4];
        float sq = a.x * a.x + a.y * a.y + a.z * a.z + a.w * a.w
                 + c.x * c.x + c.y * c.y + c.z * c.z + c.w * c.w;
        float scale = sq / (1.f + sq) * rsqrtf(sq + 1e-8f);
        a.x *= scale; a.y *= scale; a.z *= scale; a.w *= scale;
        c.x *= scale; c.y *= scale; c.z *= scale; c.w *= scale;
        int l = l0 + l_loc;
        float* dst = &g_yq[((size_t)(b * L_ + l)) * NOC1 + cp * 8];
        *(float4*)dst       = a;
        *(float4*)(dst + 4) = c;
    }
}

// ---------------------------------------------------------------------------
// Kernel 2: conv2 + 3-iter routing. 128 threads/block; each thread computes
// TWO outputs: (csaA=t>>4, asa) and (csaB=csaA+8, asa). Halves total LDS.128
// (y broadcasts feed both outputs) and total shfl — the L1-bound hot spots.
// ---------------------------------------------------------------------------
__global__ __launch_bounds__(128) void conv2_route_kernel(
    const float* __restrict__ w2, const float* __restrict__ b2,
    float* __restrict__ out)
{
    __shared__ float yq3[3][NOC1];
    __shared__ float bf[512];       // routing logits [cp][csa]
    __shared__ float ef[512];       // exp(logits)
    __shared__ float sinv[CP_];     // 1/rowsum

    const int bl = blockIdx.x;
    const int l  = bl & (L_ - 1);
    const int t  = threadIdx.x;     // 0..127

    const float* base = g_yq + (size_t)bl * NOC1;
#pragma unroll
    for (int h = 0; h < 2; h++) {
        int i = t + h * 128;
        yq3[1][i] = base[i];
        yq3[0][i] = (l > 0)      ? base[i - NOC1] : 0.f;
        yq3[2][i] = (l < L_ - 1) ? base[i + NOC1] : 0.f;
    }

    // packed conv2 weights for both outputs
    ull w2pA[12], w2pB[12];
    {
        const float2* wrA = (const float2*)(w2 + t * 24);
        const float2* wrB = (const float2*)(w2 + (t + 128) * 24);
#pragma unroll
        for (int h = 0; h < 12; h++) {
            float2 a = wrA[h], b = wrB[h];
            asm("mov.b64 %0, {%1, %2};" : "=l"(w2pA[h]) : "f"(a.x), "f"(a.y));
            asm("mov.b64 %0, {%1, %2};" : "=l"(w2pB[h]) : "f"(b.x), "f"(b.y));
        }
    }
    const float biasA = b2[t];
    const float biasB = b2[t + 128];

    bf[t]       = 0.f;
    bf[t + 128] = 0.f;
    bf[t + 256] = 0.f;
    bf[t + 384] = 0.f;
    __syncthreads();

    // V for both outputs, all cp — y loads shared between A and B
    float VA[CP_], VB[CP_];
#pragma unroll
    for (int cp = 0; cp < CP_; cp++) {
        ull accA, accB;
        asm("mov.b64 %0, {%1, %2};" : "=l"(accA) : "f"(biasA), "f"(0.f));
        asm("mov.b64 %0, {%1, %2};" : "=l"(accB) : "f"(biasB), "f"(0.f));
#pragma unroll
        for (int dh = 0; dh < 3; dh++) {
            const ulonglong2* yp = (const ulonglong2*)&yq3[dh][cp * 8];
            ulonglong2 ya = yp[0];
            ulonglong2 yb = yp[1];
            FFMA2(accA, ya.x, w2pA[dh * 4 + 0]);
            FFMA2(accA, ya.y, w2pA[dh * 4 + 1]);
            FFMA2(accA, yb.x, w2pA[dh * 4 + 2]);
            FFMA2(accA, yb.y, w2pA[dh * 4 + 3]);
            FFMA2(accB, ya.x, w2pB[dh * 4 + 0]);
            FFMA2(accB, ya.y, w2pB[dh * 4 + 1]);
            FFMA2(accB, yb.x, w2pB[dh * 4 + 2]);
            FFMA2(accB, yb.y, w2pB[dh * 4 + 3]);
        }
        float lo, hi;
        UNPACK2(lo, hi, accA); VA[cp] = lo + hi;
        UNPACK2(lo, hi, accB); VB[cp] = lo + hi;
    }

    const int csaA = t >> 4;          // 0..7
    const int asa  = t & 15;
    float vA = 0.f, vB = 0.f;

    for (int r = 0; r < 3; r++) {
        float sA, sB;
        if (r == 0) {
            sA = 0.f; sB = 0.f;
#pragma unroll
            for (int cp = 0; cp < CP_; cp++) { sA += VA[cp]; sB += VB[cp]; }
            sA *= (1.f / 16.f);
            sB *= (1.f / 16.f);
        } else {
            ef[t]       = __expf(bf[t]);
            ef[t + 128] = __expf(bf[t + 128]);
            ef[t + 256] = __expf(bf[t + 256]);
            ef[t + 384] = __expf(bf[t + 384]);
            __syncthreads();
            if (t < CP_) {
                float sum = 0.f;
#pragma unroll
                for (int j2 = 0; j2 < CSA_; j2++) sum += ef[t * 16 + j2];
                sinv[t] = 1.f / sum;
            }
            __syncthreads();
            sA = 0.f; sB = 0.f;
#pragma unroll
            for (int cp = 0; cp < CP_; cp++) {
                float si = sinv[cp];
                sA += ef[cp * 16 + csaA]     * (si * VA[cp]);
                sB += ef[cp * 16 + csaA + 8] * (si * VB[cp]);
            }
        }

        // squash over asa (16 contiguous lanes), both outputs
        float qA = sA * sA, qB = sB * sB;
        qA += __shfl_xor_sync(0xffffffffu, qA, 1);
        qB += __shfl_xor_sync(0xffffffffu, qB, 1);
        qA += __shfl_xor_sync(0xffffffffu, qA, 2);
        qB += __shfl_xor_sync(0xffffffffu, qB, 2);
        qA += __shfl_xor_sync(0xffffffffu, qA, 4);
        qB += __shfl_xor_sync(0xffffffffu, qB, 4);
        qA += __shfl_xor_sync(0xffffffffu, qA, 8);
        qB += __shfl_xor_sync(0xffffffffu, qB, 8);
        float scA = qA / (1.f + qA) * rsqrtf(qA + 1e-8f);
        float scB = qB / (1.f + qB) * rsqrtf(qB + 1e-8f);
        vA = sA * scA;
        vB = sB * scB;

        if (r < 2) {
            // a[cp][csa] = sum_asa V*v via multi-value butterfly, A then B.
            int c0 = ((asa & 1) << 4) | ((asa & 2) << 2) | (asa & 4) | ((asa & 8) >> 2);
            float val[16];
#pragma unroll
            for (int side = 0; side < 2; side++) {
                const float* V = side ? VB : VA;
                float v = side ? vB : vA;
                {
                    bool u = (asa & 1);
#pragma unroll
                    for (int i = 0; i < 16; i++) {
                        float sp = (u ? V[i] : V[16 + i]) * v;
                        float kp = (u ? V[16 + i] : V[i]) * v;
                        val[i] = kp + __shfl_xor_sync(0xffffffffu, sp, 1);
                    }
                }
                {
                    bool u = (asa & 2);
#pragma unroll
                    for (int i = 0; i < 8; i++) {
                        float sp = u ? val[i] : val[8 + i];
                        float kp = u ? val[8 + i] : val[i];
                        val[i] = kp + __shfl_xor_sync(0xffffffffu, sp, 2);
                    }
                }
                {
                    bool u = (asa & 4);
#pragma unroll
                    for (int i = 0; i < 4; i++) {
                        float sp = u ? val[i] : val[4 + i];
                        float kp = u ? val[4 + i] : val[i];
                        val[i] = kp + __shfl_xor_sync(0xffffffffu, sp, 4);
                    }
                }
                {
                    bool u = (asa & 8);
#pragma unroll
                    for (int i = 0; i < 2; i++) {
                        float sp = u ? val[i] : val[2 + i];
                        float kp = u ? val[2 + i] : val[i];
                        val[i] = kp + __shfl_xor_sync(0xffffffffu, sp, 8);
                    }
                }
                int csa = csaA + side * 8;
                bf[c0 * 16 + csa]       += val[0];
                bf[(c0 + 1) * 16 + csa] += val[1];
            }
            __syncthreads();
        }
    }

    out[(size_t)bl * 256 + t]       = vA;
    out[(size_t)bl * 256 + t + 128] = vB;
}

// ---------------------------------------------------------------------------
extern "C" void kernel_launch(void* const* d_in, const int* in_sizes, int n_in,
                              void* d_out, int out_size)
{
    const float* x  = (const float*)d_in[0];   // [8, 64, 1024]
    const float* w1 = (const float*)d_in[1];   // [256, 64, 9]
    const float* b1 = (const float*)d_in[2];   // [256]
    const float* w2 = (const float*)d_in[3];   // [256, 1, 3, 8]
    const float* b2 = (const float*)d_in[4];   // [256]
    float* out = (float*)d_out;                // [8, 16384, 16]

    prep_kernel<<<576, 256>>>(w1);
    conv1_squash_kernel<<<dim3(L_ / 16, B_), 128>>>(x, b1);
    conv2_route_kernel<<<B_ * L_, 128>>>(w2, b2, out);
}